// round 1
// baseline (speedup 1.0000x reference)
#include <cuda_runtime.h>
#include <stdint.h>

// Problem constants (fixed-shape problem)
#define NROWS 65536              // 256*256 neurons
#define BATCH 64
#define NNZ_MAX (65536 * 33)

// ---------------- device scratch (no allocations allowed) ----------------
__device__ float g_xt[NROWS * BATCH];     // x transposed: [N, 64]
__device__ int   g_counts[NROWS];
__device__ int   g_offsets[NROWS];
__device__ int   g_cursor[NROWS];
__device__ float g_csrval[NNZ_MAX];
__device__ int   g_csrcol[NNZ_MAX];

// ---------------- 1. transpose x [64, N] -> xt [N, 64] ----------------
__global__ void transpose_kernel(const float* __restrict__ x) {
    __shared__ float s[32][33];
    int n0 = blockIdx.x * 32;
    int b0 = blockIdx.y * 32;
    int tx = threadIdx.x;       // 0..31
    int ty = threadIdx.y;       // 0..7
#pragma unroll
    for (int k = 0; k < 4; k++) {
        int b = ty + k * 8;
        s[b][tx] = x[(size_t)(b0 + b) * NROWS + n0 + tx];
    }
    __syncthreads();
#pragma unroll
    for (int k = 0; k < 4; k++) {
        int n = ty + k * 8;
        // xt[n0+n][b0+tx] = x[b0+tx][n0+n]
        g_xt[(size_t)(n0 + n) * BATCH + b0 + tx] = s[tx][n];
    }
}

// ---------------- 2. zero counts ----------------
__global__ void zero_kernel() {
    int i = blockIdx.x * blockDim.x + threadIdx.x;
    if (i < NROWS) g_counts[i] = 0;
}

// ---------------- 3. histogram of destination rows ----------------
__global__ void hist_kernel(const int* __restrict__ rows, int nnz) {
    int e = blockIdx.x * blockDim.x + threadIdx.x;
    if (e < nnz) atomicAdd(&g_counts[rows[e]], 1);
}

// ---------------- 4. exclusive scan (single block, 1024 threads) ----------------
__global__ void scan_kernel() {
    __shared__ int sums[1024];
    int t = threadIdx.x;
    int base = t * (NROWS / 1024);   // 64 elements per thread
    int s = 0;
#pragma unroll 4
    for (int i = 0; i < NROWS / 1024; i++) s += g_counts[base + i];
    sums[t] = s;
    __syncthreads();
    // Hillis-Steele inclusive scan over 1024 partials
    for (int d = 1; d < 1024; d <<= 1) {
        int v = (t >= d) ? sums[t - d] : 0;
        __syncthreads();
        sums[t] += v;
        __syncthreads();
    }
    int run = (t == 0) ? 0 : sums[t - 1];   // exclusive prefix
#pragma unroll 4
    for (int i = 0; i < NROWS / 1024; i++) {
        g_offsets[base + i] = run;
        g_cursor[base + i]  = run;
        run += g_counts[base + i];
    }
}

// ---------------- 5. scatter edges into CSR-by-destination ----------------
__global__ void scatter_kernel(const int* __restrict__ rows,
                               const int* __restrict__ cols,
                               const float* __restrict__ vals, int nnz) {
    int e = blockIdx.x * blockDim.x + threadIdx.x;
    if (e < nnz) {
        int r = rows[e];
        int pos = atomicAdd(&g_cursor[r], 1);
        g_csrval[pos] = vals[e];
        g_csrcol[pos] = cols[e];
    }
}

// ---------------- 6. gather SpMM: out[b, r] = sum_e v_e * xt[col_e][b] ----------------
// Block = 256 threads (8 warps) handles 32 consecutive output rows.
// Warp w handles rows r0 + w + {0,8,16,24}. Lane l accumulates batch (2l, 2l+1).
// Output staged in smem so global writes are coalesced 128B runs of out[b, r0..r0+31].
__global__ void spmm_kernel(float* __restrict__ out) {
    __shared__ float tile[32 * 65];   // [row_local][b], stride 65 kills bank conflicts
    int t = threadIdx.x;
    int warp = t >> 5;
    int lane = t & 31;
    int r0 = blockIdx.x * 32;

#pragma unroll
    for (int k = 0; k < 4; k++) {
        int row_local = warp + k * 8;
        int r = r0 + row_local;
        int start = g_offsets[r];
        int cnt = g_counts[r];
        float accx = 0.f, accy = 0.f;
        for (int i = 0; i < cnt; i++) {
            float v = __ldg(&g_csrval[start + i]);
            int   c = __ldg(&g_csrcol[start + i]);
            const float2 xv = *reinterpret_cast<const float2*>(
                &g_xt[((size_t)c << 6) + (lane << 1)]);
            accx = fmaf(v, xv.x, accx);
            accy = fmaf(v, xv.y, accy);
        }
        tile[row_local * 65 + (lane << 1)]     = accx;
        tile[row_local * 65 + (lane << 1) + 1] = accy;
    }
    __syncthreads();
#pragma unroll
    for (int k = 0; k < 8; k++) {
        int idx = k * 256 + t;
        int b = idx >> 5;        // 0..63
        int c = idx & 31;        // 0..31
        out[(size_t)b * NROWS + r0 + c] = tile[c * 65 + b];
    }
}

// ---------------- launch ----------------
extern "C" void kernel_launch(void* const* d_in, const int* in_sizes, int n_in,
                              void* d_out, int out_size) {
    const float* x    = (const float*)d_in[0];   // [64, 65536]
    const float* vals = (const float*)d_in[1];   // [NNZ]
    const int*   rows = (const int*)d_in[2];     // [NNZ] int32
    const int*   cols = (const int*)d_in[3];     // [NNZ] int32
    float* out = (float*)d_out;                  // [64, 65536]
    int nnz = in_sizes[1];

    // transpose x -> xt [N, 64]
    {
        dim3 blk(32, 8);
        dim3 grd(NROWS / 32, BATCH / 32);
        transpose_kernel<<<grd, blk>>>(x);
    }
    // CSR build
    zero_kernel<<<NROWS / 256, 256>>>();
    hist_kernel<<<(nnz + 255) / 256, 256>>>(rows, nnz);
    scan_kernel<<<1, 1024>>>();
    scatter_kernel<<<(nnz + 255) / 256, 256>>>(rows, cols, vals, nnz);
    // gather SpMM
    spmm_kernel<<<NROWS / 32, 256>>>(out);
}

// round 2
// speedup vs baseline: 2.1772x; 2.1772x over previous
#include <cuda_runtime.h>
#include <stdint.h>

// Problem constants (fixed-shape problem)
#define NROWS 65536              // 256*256 neurons
#define BATCH 64
#define CAP   1024               // ELL row capacity (corner rows reach ~650 due to clamping)

// ---------------- device scratch (static; no runtime allocation) ----------------
__device__ float  g_xt[NROWS * BATCH];           // x transposed: [N, 64]
__device__ int    g_counts[NROWS];               // per-destination-row edge count
__device__ float2 g_ell[(size_t)NROWS * CAP];    // (value, col-as-bits) per slot

// ---------------- 1. transpose x [64, N] -> xt [N, 64] ----------------
__global__ void transpose_kernel(const float* __restrict__ x) {
    __shared__ float s[32][33];
    int n0 = blockIdx.x * 32;
    int b0 = blockIdx.y * 32;
    int tx = threadIdx.x;       // 0..31
    int ty = threadIdx.y;       // 0..7
#pragma unroll
    for (int k = 0; k < 4; k++) {
        int b = ty + k * 8;
        s[b][tx] = x[(size_t)(b0 + b) * NROWS + n0 + tx];
    }
    __syncthreads();
#pragma unroll
    for (int k = 0; k < 4; k++) {
        int n = ty + k * 8;
        g_xt[(size_t)(n0 + n) * BATCH + b0 + tx] = s[tx][n];
    }
}

// ---------------- 2. zero counts ----------------
__global__ void zero_kernel() {
    int i = blockIdx.x * blockDim.x + threadIdx.x;
    if (i < NROWS) g_counts[i] = 0;
}

// ---------------- 3. scatter edges into ELL (histogram fused into scatter) ----------------
__global__ void scatter_kernel(const int* __restrict__ rows,
                               const int* __restrict__ cols,
                               const float* __restrict__ vals, int nnz) {
    int e = blockIdx.x * blockDim.x + threadIdx.x;
    if (e < nnz) {
        int r = rows[e];
        int pos = atomicAdd(&g_counts[r], 1);
        if (pos < CAP) {
            g_ell[((size_t)r << 10) + pos] =
                make_float2(vals[e], __int_as_float(cols[e]));
        }
    }
}

// ---------------- 4. gather SpMM: out[b, r] = sum_e v_e * xt[col_e][b] ----------------
// Block = 256 threads (8 warps) handles 32 consecutive output rows.
// Warp w handles rows r0 + w + {0,8,16,24}. Lane l accumulates batch (2l, 2l+1).
// Output staged in smem so global writes are coalesced 128B runs of out[b, r0..r0+31].
__global__ void spmm_kernel(float* __restrict__ out) {
    __shared__ float tile[32 * 65];   // [row_local][b], stride 65 kills bank conflicts
    int t = threadIdx.x;
    int warp = t >> 5;
    int lane = t & 31;
    int r0 = blockIdx.x * 32;

#pragma unroll
    for (int k = 0; k < 4; k++) {
        int row_local = warp + k * 8;
        int r = r0 + row_local;
        int cnt = g_counts[r];
        if (cnt > CAP) cnt = CAP;
        const float2* __restrict__ ell = &g_ell[(size_t)r << 10];
        float accx = 0.f, accy = 0.f;
        for (int i = 0; i < cnt; i++) {
            float2 vc = __ldg(&ell[i]);                 // warp-uniform broadcast
            int c = __float_as_int(vc.y);
            const float2 xv = *reinterpret_cast<const float2*>(
                &g_xt[((size_t)c << 6) + (lane << 1)]); // coalesced 256B/warp
            accx = fmaf(vc.x, xv.x, accx);
            accy = fmaf(vc.x, xv.y, accy);
        }
        tile[row_local * 65 + (lane << 1)]     = accx;
        tile[row_local * 65 + (lane << 1) + 1] = accy;
    }
    __syncthreads();
#pragma unroll
    for (int k = 0; k < 8; k++) {
        int idx = k * 256 + t;
        int b = idx >> 5;        // 0..63
        int c = idx & 31;        // 0..31
        out[(size_t)b * NROWS + r0 + c] = tile[c * 65 + b];
    }
}

// ---------------- launch ----------------
extern "C" void kernel_launch(void* const* d_in, const int* in_sizes, int n_in,
                              void* d_out, int out_size) {
    const float* x    = (const float*)d_in[0];   // [64, 65536]
    const float* vals = (const float*)d_in[1];   // [NNZ]
    const int*   rows = (const int*)d_in[2];     // [NNZ] int32
    const int*   cols = (const int*)d_in[3];     // [NNZ] int32
    float* out = (float*)d_out;                  // [64, 65536]
    int nnz = in_sizes[1];

    // transpose x -> xt [N, 64]
    {
        dim3 blk(32, 8);
        dim3 grd(NROWS / 32, BATCH / 32);
        transpose_kernel<<<grd, blk>>>(x);
    }
    // ELL build: zero counts, then scatter (histogram fused)
    zero_kernel<<<NROWS / 256, 256>>>();
    scatter_kernel<<<(nnz + 255) / 256, 256>>>(rows, cols, vals, nnz);
    // gather SpMM
    spmm_kernel<<<NROWS / 32, 256>>>(out);
}